// round 1
// baseline (speedup 1.0000x reference)
#include <cuda_runtime.h>

// ---------------------------------------------------------------------------
// SymmetricContraction: out[b,c,m] = cubic polynomial in A[b,c,0..8]
//   out[b,c,m] = sum_i  S1[c,m,i]      * A_i
//              + sum_{i<=j} S2[c,m,ij] * A_i A_j
//              + sum_{i<=j<=l} S3[c,m,ijl] * A_i A_j A_l
// with S* = symmetrized (U contracted with w) per channel c.
// m-order matches the reference concat: [s(1), p(3), d(5)] = 9 outputs.
// ---------------------------------------------------------------------------

#define NC 128        // channels
#define NB 2048       // nodes
#define NI 9          // irreps dim
#define NT 219        // 9 singles + 45 pairs + 165 triples
#define ROWP 12       // padded row (floats) -> 48B, 16B aligned

static __device__ float g_S[NC * NT * ROWP];   // ~1.35 MB scratch

// ---------------------------------------------------------------------------
// Kernel 1: precompute symmetrized per-channel tensors S[c][t][0..8]
// ---------------------------------------------------------------------------
__global__ void prep_kernel(
    const float* __restrict__ Us1, const float* __restrict__ Us2, const float* __restrict__ Us3,
    const float* __restrict__ Up1, const float* __restrict__ Up2, const float* __restrict__ Up3,
    const float* __restrict__ Ud1, const float* __restrict__ Ud2, const float* __restrict__ Ud3,
    const float* __restrict__ ws1, const float* __restrict__ ws2, const float* __restrict__ ws3,
    const float* __restrict__ wp1, const float* __restrict__ wp2, const float* __restrict__ wp3,
    const float* __restrict__ wd1, const float* __restrict__ wd2, const float* __restrict__ wd3)
{
    int gid = blockIdx.x * blockDim.x + threadIdx.x;
    if (gid >= NC * NT) return;
    int c = gid / NT;
    int t = gid % NT;

    float v[9];
#pragma unroll
    for (int q = 0; q < 9; q++) v[q] = 0.f;

    if (t < 9) {
        // degree-1: U [m, 9, k=1], w [1, 128]
        int i = t;
        v[0] = Us1[i] * ws1[c];
        for (int m = 0; m < 3; m++) v[1 + m] = Up1[m * 9 + i] * wp1[c];
        for (int m = 0; m < 5; m++) v[4 + m] = Ud1[m * 9 + i] * wd1[c];
    } else if (t < 54) {
        // degree-2 pair (i<=j)
        int rem = t - 9, i = 0, j = 0;
        for (i = 0; i < 9; i++) { int cnt = 9 - i; if (rem < cnt) { j = i + rem; break; } rem -= cnt; }
        int pa[2] = { i, j }, pb[2] = { j, i };
        float inv = (i == j) ? 0.5f : 1.0f;  // sum over 2 perms / multiplicity
        {   // s: U_s2 [1,9,9,2]
            float s = 0.f;
            for (int p = 0; p < 2; p++)
                for (int k = 0; k < 2; k++)
                    s += Us2[(pa[p] * 9 + pb[p]) * 2 + k] * ws2[k * NC + c];
            v[0] = s * inv;
        }
        for (int m = 0; m < 3; m++) {   // p: [3,9,9,3]
            float s = 0.f;
            for (int p = 0; p < 2; p++)
                for (int k = 0; k < 3; k++)
                    s += Up2[((m * 9 + pa[p]) * 9 + pb[p]) * 3 + k] * wp2[k * NC + c];
            v[1 + m] = s * inv;
        }
        for (int m = 0; m < 5; m++) {   // d: [5,9,9,4]
            float s = 0.f;
            for (int p = 0; p < 2; p++)
                for (int k = 0; k < 4; k++)
                    s += Ud2[((m * 9 + pa[p]) * 9 + pb[p]) * 4 + k] * wd2[k * NC + c];
            v[4 + m] = s * inv;
        }
    } else {
        // degree-3 triple (i<=j<=l)
        int rem = t - 54, i = 0, j = 0, l = 0;
        for (i = 0; i < 9; i++) { int cnt = (9 - i) * (10 - i) / 2; if (rem < cnt) break; rem -= cnt; }
        for (j = i; j < 9; j++) { int cnt = 9 - j; if (rem < cnt) { l = j + rem; break; } rem -= cnt; }
        float inv;
        if (i == j && j == l)                 inv = 1.0f / 6.0f;  // 6 perms / mult 6
        else if (i == j || j == l || i == l)  inv = 0.5f;         // 6 perms / mult 2
        else                                  inv = 1.0f;
        int P0[6] = { i,i,j,j,l,l }, P1[6] = { j,l,i,l,i,j }, P2i[6] = { l,j,l,i,j,i };
        {   // s: U_s3 [1,9,9,9,5]
            float s = 0.f;
            for (int p = 0; p < 6; p++)
                for (int k = 0; k < 5; k++)
                    s += Us3[((P0[p] * 9 + P1[p]) * 9 + P2i[p]) * 5 + k] * ws3[k * NC + c];
            v[0] = s * inv;
        }
        for (int m = 0; m < 3; m++) {   // p: [3,9,9,9,8]
            float s = 0.f;
            for (int p = 0; p < 6; p++)
                for (int k = 0; k < 8; k++)
                    s += Up3[(((m * 9 + P0[p]) * 9 + P1[p]) * 9 + P2i[p]) * 8 + k] * wp3[k * NC + c];
            v[1 + m] = s * inv;
        }
        for (int m = 0; m < 5; m++) {   // d: [5,9,9,9,10]
            float s = 0.f;
            for (int p = 0; p < 6; p++)
                for (int k = 0; k < 10; k++)
                    s += Ud3[(((m * 9 + P0[p]) * 9 + P1[p]) * 9 + P2i[p]) * 10 + k] * wd3[k * NC + c];
            v[4 + m] = s * inv;
        }
    }

    float* dst = g_S + (c * NT + t) * ROWP;
#pragma unroll
    for (int q = 0; q < 9; q++) dst[q] = v[q];
    dst[9] = 0.f; dst[10] = 0.f; dst[11] = 0.f;
}

// ---------------------------------------------------------------------------
// Kernel 2: hot loop. One block per channel c, one thread per node b.
// All smem loads are warp-uniform -> broadcast LDS.128 (no conflicts).
// ---------------------------------------------------------------------------
__device__ __forceinline__ void fma9(float acc[9], const float* __restrict__ row, float mono)
{
    float4 r0 = *reinterpret_cast<const float4*>(row);
    float4 r1 = *reinterpret_cast<const float4*>(row + 4);
    float  r8 = row[8];
    acc[0] = fmaf(r0.x, mono, acc[0]);
    acc[1] = fmaf(r0.y, mono, acc[1]);
    acc[2] = fmaf(r0.z, mono, acc[2]);
    acc[3] = fmaf(r0.w, mono, acc[3]);
    acc[4] = fmaf(r1.x, mono, acc[4]);
    acc[5] = fmaf(r1.y, mono, acc[5]);
    acc[6] = fmaf(r1.z, mono, acc[6]);
    acc[7] = fmaf(r1.w, mono, acc[7]);
    acc[8] = fmaf(r8,  mono, acc[8]);
}

__global__ __launch_bounds__(256) void sc_main_kernel(
    const float* __restrict__ A, float* __restrict__ out)
{
    __shared__ __align__(16) float sS[NT * ROWP];

    int c = blockIdx.x;
    const float* gS = g_S + c * NT * ROWP;
    for (int idx = threadIdx.x; idx < NT * ROWP; idx += 256)
        sS[idx] = gS[idx];
    __syncthreads();

    int b = blockIdx.y * 256 + threadIdx.x;        // grid.y * 256 == NB exactly
    const float* Ap = A + (b * NC + c) * NI;

    float a[9];
#pragma unroll
    for (int i = 0; i < 9; i++) a[i] = __ldg(Ap + i);

    float acc[9];
#pragma unroll
    for (int q = 0; q < 9; q++) acc[q] = 0.f;

    // ---- degree 1: rows 0..8
#pragma unroll
    for (int i = 0; i < 9; i++)
        fma9(acc, sS + i * ROWP, a[i]);

    // ---- degree 2: rows 9..53, build pair products P2
    float P2[45];
#pragma unroll
    for (int i = 0; i < 9; i++) {
#pragma unroll
        for (int j = i; j < 9; j++) {
            int pidx = i * 9 - (i * (i - 1)) / 2 + (j - i);   // compile-time constant
            P2[pidx] = a[i] * a[j];
            fma9(acc, sS + (9 + pidx) * ROWP, P2[pidx]);
        }
    }

    // ---- degree 3: rows 54..218
    int trow = 54;                                            // folded by full unroll
#pragma unroll
    for (int i = 0; i < 9; i++) {
#pragma unroll
        for (int j = i; j < 9; j++) {
            int pidx = i * 9 - (i * (i - 1)) / 2 + (j - i);
#pragma unroll
            for (int l = j; l < 9; l++) {
                float mono = P2[pidx] * a[l];
                fma9(acc, sS + trow * ROWP, mono);
                trow++;
            }
        }
    }

    float* op = out + (b * NC + c) * NI;
#pragma unroll
    for (int q = 0; q < 9; q++) op[q] = acc[q];
}

// ---------------------------------------------------------------------------
// Launch: resolve inputs by element count (ordering-agnostic).
// ---------------------------------------------------------------------------
extern "C" void kernel_launch(void* const* d_in, const int* in_sizes, int n_in,
                              void* d_out, int out_size)
{
    const float* A = nullptr;
    const float* U[3][3] = {};   // [type s/p/d][nu-1]
    const float* W[3][3] = {};   // [type s/p/d][nu-1]

    // w_*2 sizes are unique (256/384/512); their appearance order gives the
    // type order of any naming-consistent metadata ordering. Apply the same
    // order to the three ambiguous size-128 entries (w_*1).
    int typeorder[3] = { 0, 1, 2 };
    int to_n = 0;
    int w1_idx[3]; int w1_n = 0;

    for (int idx = 0; idx < n_in; idx++) {
        int s = in_sizes[idx];
        const float* p = (const float*)d_in[idx];
        switch (s) {
            case NB * NC * NI: A = p; break;
            case 9:     U[0][0] = p; break;   // U_s1 (1,9,1)
            case 162:   U[0][1] = p; break;   // U_s2 (1,9,9,2)
            case 3645:  U[0][2] = p; break;   // U_s3 (1,9,9,9,5)
            case 27:    U[1][0] = p; break;   // U_p1 (3,9,1)
            case 729:   U[1][1] = p; break;   // U_p2 (3,9,9,3)
            case 17496: U[1][2] = p; break;   // U_p3 (3,9,9,9,8)
            case 45:    U[2][0] = p; break;   // U_d1 (5,9,1)
            case 1620:  U[2][1] = p; break;   // U_d2 (5,9,9,4)
            case 36450: U[2][2] = p; break;   // U_d3 (5,9,9,9,10)
            case 256:   W[0][1] = p; if (to_n < 3) typeorder[to_n++] = 0; break; // w_s2
            case 384:   W[1][1] = p; if (to_n < 3) typeorder[to_n++] = 1; break; // w_p2
            case 512:   W[2][1] = p; if (to_n < 3) typeorder[to_n++] = 2; break; // w_d2
            case 640:   W[0][2] = p; break;   // w_s3
            case 1024:  W[1][2] = p; break;   // w_p3
            case 1280:  W[2][2] = p; break;   // w_d3
            case 128:   if (w1_n < 3) w1_idx[w1_n++] = idx; break; // w_*1 (ambiguous)
            default: break;
        }
    }
    for (int q = 0; q < 3 && q < w1_n; q++)
        W[typeorder[q]][0] = (const float*)d_in[w1_idx[q]];

    // Kernel 1: per-channel symmetrized tensors
    {
        int nthreads = NC * NT;
        prep_kernel<<<(nthreads + 255) / 256, 256>>>(
            U[0][0], U[0][1], U[0][2],
            U[1][0], U[1][1], U[1][2],
            U[2][0], U[2][1], U[2][2],
            W[0][0], W[0][1], W[0][2],
            W[1][0], W[1][1], W[1][2],
            W[2][0], W[2][1], W[2][2]);
    }

    // Kernel 2: main contraction
    dim3 grid(NC, NB / 256);
    sc_main_kernel<<<grid, 256>>>(A, (float*)d_out);
}